// round 5
// baseline (speedup 1.0000x reference)
#include <cuda_runtime.h>

#define DIM 31
#define PAD 32
#define NMAX 500000
#define EMAX 2000000
#define GMAX 4096
#define BN_EPS 1e-5f
#define NPB_MAX 4096

typedef unsigned long long u64;

#define PACK2(d, lo, hi) \
    asm("mov.b64 %0, {%1, %2};" : "=l"(d) : "r"(__float_as_uint(lo)), "r"(__float_as_uint(hi)))
#define UNPACK2(lo, hi, s)                                  \
    do {                                                    \
        unsigned _l, _h;                                    \
        asm("mov.b64 {%0, %1}, %2;" : "=r"(_l), "=r"(_h) : "l"(s)); \
        lo = __uint_as_float(_l);                           \
        hi = __uint_as_float(_h);                           \
    } while (0)
#define FMA2(d, a, b, c) \
    asm("fma.rn.f32x2 %0, %1, %2, %3;" : "=l"(d) : "l"(a), "l"(b), "l"(c))

// ---------------- scratch ----------------
__device__ float g_y0[(size_t)NMAX * PAD];    // ping
__device__ float g_y1[(size_t)NMAX * PAD];    // pong
__device__ int   g_cnt[NMAX];
__device__ int   g_rowptr[NMAX + 1];
__device__ int   g_cursor[NMAX];
__device__ int   g_perm[EMAX];
__device__ int   g_bsums[1024];
__device__ float g_partial[(size_t)NPB_MAX * 64];  // per-block column stats
__device__ float g_sums[5 * 64];              // per-layer colsum (c) + sumsq (32+c)
__device__ float g_pooled[GMAX * PAD];
__device__ float g_gcnt[GMAX];
__device__ float g_ha[GMAX * 256];
__device__ float g_hb[GMAX * 256];
__device__ float g_c1[GMAX * 1024];
__device__ float g_c2[GMAX * 256];

// ---------------- init: pack x into g_y0, zero cnt/pooled/gcnt ----------------
__global__ void k_init(const float* __restrict__ x, int N) {
    int stride = gridDim.x * blockDim.x;
    int tid0 = blockIdx.x * blockDim.x + threadIdx.x;
    int total = N * PAD;
    for (int t = tid0; t < total; t += stride) {
        int c = t & (PAD - 1);
        int i = t >> 5;
        g_y0[t] = (c < DIM) ? x[i * DIM + c] : 0.f;
    }
    for (int t = tid0; t < N; t += stride) g_cnt[t] = 0;
    for (int t = tid0; t < GMAX * PAD; t += stride) g_pooled[t] = 0.f;
    for (int t = tid0; t < GMAX; t += stride) g_gcnt[t] = 0.f;
}

// ---------------- CSR build ----------------
__global__ void k_count(const int* __restrict__ dst, int E) {
    for (int e = blockIdx.x * blockDim.x + threadIdx.x; e < E;
         e += gridDim.x * blockDim.x)
        atomicAdd(&g_cnt[__ldg(dst + e)], 1);
}

__global__ void k_scan1(int N) {
    __shared__ int s[512];
    int i = blockIdx.x * 512 + threadIdx.x;
    s[threadIdx.x] = (i < N) ? g_cnt[i] : 0;
    __syncthreads();
    for (int o = 256; o > 0; o >>= 1) {
        if (threadIdx.x < o) s[threadIdx.x] += s[threadIdx.x + o];
        __syncthreads();
    }
    if (threadIdx.x == 0) g_bsums[blockIdx.x] = s[0];
}

__global__ void k_scan2(int NB) {
    __shared__ int s[1024];
    int i = threadIdx.x;
    int v = (i < NB) ? g_bsums[i] : 0;
    s[i] = v;
    __syncthreads();
    for (int o = 1; o < 1024; o <<= 1) {
        int t = (i >= o) ? s[i - o] : 0;
        __syncthreads();
        s[i] += t;
        __syncthreads();
    }
    if (i < NB) g_bsums[i] = s[i] - v;  // exclusive
}

__global__ void k_scan3(int N) {
    __shared__ int s[512];
    int i = blockIdx.x * 512 + threadIdx.x;
    int c = (i < N) ? g_cnt[i] : 0;
    s[threadIdx.x] = c;
    __syncthreads();
    for (int o = 1; o < 512; o <<= 1) {
        int t = (threadIdx.x >= o) ? s[threadIdx.x - o] : 0;
        __syncthreads();
        s[threadIdx.x] += t;
        __syncthreads();
    }
    int ex = s[threadIdx.x] - c + g_bsums[blockIdx.x];
    if (i < N) {
        g_rowptr[i] = ex;
        g_cursor[i] = ex;
        if (i == N - 1) g_rowptr[N] = ex + c;
    }
}

__global__ void k_fill(const int* __restrict__ src, const int* __restrict__ dst, int E) {
    for (int e = blockIdx.x * blockDim.x + threadIdx.x; e < E;
         e += gridDim.x * blockDim.x) {
        int d = __ldg(dst + e);
        int p = atomicAdd(&g_cursor[d], 1);
        g_perm[p] = __ldg(src + e);
    }
}

// ---------------- fused gather + BN-affine + MLP + stats (double-buffered) ----------------
__global__ void __launch_bounds__(128) k_gmlp(const float* __restrict__ yin,
                                              float* __restrict__ yout,
                                              const float* __restrict__ W1,
                                              const float* __restrict__ b1,
                                              const float* __restrict__ W2,
                                              const float* __restrict__ b2,
                                              const float* __restrict__ gammaP,
                                              const float* __restrict__ betaP,
                                              const float* __restrict__ sumsP,
                                              float* __restrict__ partial,
                                              int N, float invN) {
    __shared__ float hbuf[128 * 33];           // per-node gathered sums; col 32 = deg
    __shared__ u64 sW1p[31 * 16], sW2p[31 * 16];
    __shared__ u64 sb1p[16], sb2p[16];
    __shared__ float ssc[32], ssf[32];
    __shared__ float sstat[4 * 64];

    // ---- load & pack weights ----
    for (int idx = threadIdx.x; idx < 31 * 16; idx += 128) {
        int i = idx >> 4, o = idx & 15;
        float lo = W1[i * 31 + 2 * o];
        float hi = (2 * o + 1 < 31) ? W1[i * 31 + 2 * o + 1] : 0.f;
        u64 p;
        PACK2(p, lo, hi);
        sW1p[idx] = p;
        lo = W2[i * 31 + 2 * o];
        hi = (2 * o + 1 < 31) ? W2[i * 31 + 2 * o + 1] : 0.f;
        PACK2(p, lo, hi);
        sW2p[idx] = p;
    }
    if (threadIdx.x < 16) {
        int o = threadIdx.x;
        float lo = b1[2 * o];
        float hi = (2 * o + 1 < 31) ? b1[2 * o + 1] : 0.f;
        u64 p;
        PACK2(p, lo, hi);
        sb1p[o] = p;
        lo = b2[2 * o];
        hi = (2 * o + 1 < 31) ? b2[2 * o + 1] : 0.f;
        PACK2(p, lo, hi);
        sb2p[o] = p;
    }
    if (threadIdx.x < 32) {
        int c = threadIdx.x;
        float sc = 0.f, sf = 0.f;
        if (c < DIM) {
            sc = 1.f;
            if (sumsP) {
                float m = sumsP[c] * invN;
                float var = sumsP[PAD + c] * invN - m * m;
                float istd = rsqrtf(var + BN_EPS);
                sc = gammaP[c] * istd;
                sf = betaP[c] - m * sc;
            }
        }
        ssc[c] = sc;
        ssf[c] = sf;
    }

    int base = blockIdx.x * 128;

    // ---- phase A: gather self + neighbor sums (from yin) into smem ----
    int gg = threadIdx.x & 7;
    int sub = threadIdx.x >> 3;
#pragma unroll
    for (int pass = 0; pass < 8; pass++) {
        int ln = pass * 16 + sub;
        int n = base + ln;
        float4 acc = make_float4(0.f, 0.f, 0.f, 0.f);
        int deg = 0;
        if (n < N) {
            int beg = __ldg(g_rowptr + n), end = __ldg(g_rowptr + n + 1);
            deg = end - beg;
            acc = ((const float4*)yin)[(size_t)n * 8 + gg];
            int p = beg;
            for (; p + 1 < end; p += 2) {
                int s0 = __ldg(g_perm + p);
                int s1 = __ldg(g_perm + p + 1);
                float4 v0 = *(const float4*)(yin + (size_t)s0 * PAD + gg * 4);
                float4 v1 = *(const float4*)(yin + (size_t)s1 * PAD + gg * 4);
                acc.x += v0.x + v1.x;
                acc.y += v0.y + v1.y;
                acc.z += v0.z + v1.z;
                acc.w += v0.w + v1.w;
            }
            if (p < end) {
                int s0 = __ldg(g_perm + p);
                float4 v0 = *(const float4*)(yin + (size_t)s0 * PAD + gg * 4);
                acc.x += v0.x;
                acc.y += v0.y;
                acc.z += v0.z;
                acc.w += v0.w;
            }
        }
        float* hp = hbuf + ln * 33;
        hp[gg * 4 + 0] = acc.x;
        hp[gg * 4 + 1] = acc.y;
        hp[gg * 4 + 2] = acc.z;
        hp[gg * 4 + 3] = acc.w;
        if (gg == 7) hp[32] = (float)deg;
    }
    __syncthreads();

    // ---- phase B: MLP per thread (f32x2 packed) ----
    int n = base + threadIdx.x;
    bool act = n < N;
    const float* hp = hbuf + threadIdx.x * 33;
    float dp1 = hp[32] + 1.f;

    u64 acc2[16];
#pragma unroll
    for (int o = 0; o < 16; o++) acc2[o] = sb1p[o];
#pragma unroll
    for (int i = 0; i < 31; i++) {
        float xi = ssc[i] * hp[i] + dp1 * ssf[i];
        u64 xp;
        PACK2(xp, xi, xi);
        const u64* wr = sW1p + i * 16;
#pragma unroll
        for (int o = 0; o < 16; o++) FMA2(acc2[o], xp, wr[o], acc2[o]);
    }
    float tt[31];
#pragma unroll
    for (int o = 0; o < 16; o++) {
        float lo, hi;
        UNPACK2(lo, hi, acc2[o]);
        tt[2 * o] = fmaxf(lo, 0.f);
        if (2 * o + 1 < 31) tt[2 * o + 1] = fmaxf(hi, 0.f);
    }
#pragma unroll
    for (int o = 0; o < 16; o++) acc2[o] = sb2p[o];
#pragma unroll
    for (int i = 0; i < 31; i++) {
        float xi = tt[i];
        u64 xp;
        PACK2(xp, xi, xi);
        const u64* wr = sW2p + i * 16;
#pragma unroll
        for (int o = 0; o < 16; o++) FMA2(acc2[o], xp, wr[o], acc2[o]);
    }

    float yv[32];
#pragma unroll
    for (int o = 0; o < 16; o++) {
        float lo, hi;
        UNPACK2(lo, hi, acc2[o]);
        yv[2 * o] = act ? fmaxf(lo, 0.f) : 0.f;
        yv[2 * o + 1] = act ? fmaxf(hi, 0.f) : 0.f;
    }
    yv[31] = 0.f;

    if (act) {
        float4* outp = (float4*)(yout + (size_t)n * PAD);
#pragma unroll
        for (int g = 0; g < 8; g++)
            outp[g] = make_float4(yv[4 * g], yv[4 * g + 1], yv[4 * g + 2], yv[4 * g + 3]);
    }

    // ---- column stats: butterfly -> per-warp smem rows -> per-block partials ----
    int wid = threadIdx.x >> 5, lane = threadIdx.x & 31;
#pragma unroll
    for (int c = 0; c < 31; c++) {
        float s = yv[c];
        float q = s * s;
#pragma unroll
        for (int o = 16; o > 0; o >>= 1) {
            s += __shfl_xor_sync(0xffffffffu, s, o);
            q += __shfl_xor_sync(0xffffffffu, q, o);
        }
        if (lane == 0) {
            sstat[wid * 64 + c] = s;
            sstat[wid * 64 + 32 + c] = q;
        }
    }
    if (lane == 0) {
        sstat[wid * 64 + 31] = 0.f;
        sstat[wid * 64 + 63] = 0.f;
    }
    __syncthreads();
    if (threadIdx.x < 64) {
        float t = sstat[threadIdx.x] + sstat[64 + threadIdx.x] +
                  sstat[128 + threadIdx.x] + sstat[192 + threadIdx.x];
        partial[(size_t)blockIdx.x * 64 + threadIdx.x] = t;
    }
}

// ---------------- reduce per-block partials into g_sums[l*64..] ----------------
__global__ void k_reduce(float* __restrict__ out, int NPB) {
    int slot = blockIdx.x;  // 64 blocks
    float s = 0.f;
    for (int i = threadIdx.x; i < NPB; i += blockDim.x)
        s += g_partial[(size_t)i * 64 + slot];
#pragma unroll
    for (int o = 16; o > 0; o >>= 1) s += __shfl_xor_sync(0xffffffffu, s, o);
    __shared__ float sh[8];
    if ((threadIdx.x & 31) == 0) sh[threadIdx.x >> 5] = s;
    __syncthreads();
    if (threadIdx.x == 0) {
        float t = 0.f;
#pragma unroll
        for (int w = 0; w < 8; w++) t += sh[w];
        out[slot] = t;
    }
}

// ---------------- pooling: raw sums + counts, warp-aggregated ----------------
__global__ void k_pool(const float* __restrict__ yin, const int* __restrict__ batch, int N) {
    int t = blockIdx.x * blockDim.x + threadIdx.x;
    int n = t >> 3, g = t & 7, lane = threadIdx.x & 31;
    int b = -1;
    float4 v = make_float4(0.f, 0.f, 0.f, 0.f);
    if (n < N) {
        b = __ldg(batch + n);
        v = ((const float4*)yin)[(size_t)n * 8 + g];
    }
    int b1 = __shfl_xor_sync(0xffffffffu, b, 8);
    int b2 = __shfl_xor_sync(0xffffffffu, b, 16);
    int b3 = __shfl_xor_sync(0xffffffffu, b, 24);
    bool allsame = (b == b1) && (b == b2) && (b == b3);
    if (allsame) {
        v.x += __shfl_xor_sync(0xffffffffu, v.x, 8);
        v.y += __shfl_xor_sync(0xffffffffu, v.y, 8);
        v.z += __shfl_xor_sync(0xffffffffu, v.z, 8);
        v.w += __shfl_xor_sync(0xffffffffu, v.w, 8);
        v.x += __shfl_xor_sync(0xffffffffu, v.x, 16);
        v.y += __shfl_xor_sync(0xffffffffu, v.y, 16);
        v.z += __shfl_xor_sync(0xffffffffu, v.z, 16);
        v.w += __shfl_xor_sync(0xffffffffu, v.w, 16);
        if (b >= 0 && lane < 8) {
            float* p = g_pooled + (size_t)b * PAD + g * 4;
            atomicAdd(p + 0, v.x);
            atomicAdd(p + 1, v.y);
            atomicAdd(p + 2, v.z);
            if (g < 7) atomicAdd(p + 3, v.w);
            if (lane == 0) atomicAdd(&g_gcnt[b], 4.f);
        }
    } else {
        if (b >= 0) {
            float* p = g_pooled + (size_t)b * PAD + g * 4;
            atomicAdd(p + 0, v.x);
            atomicAdd(p + 1, v.y);
            atomicAdd(p + 2, v.z);
            if (g < 7) atomicAdd(p + 3, v.w);
            if (g == 0) atomicAdd(&g_gcnt[b], 1.f);
        }
    }
}

// ---------------- per-graph fc with layer-4 BN affine applied to pooled ----------------
__global__ void k_fcbr(const float* __restrict__ W, const float* __restrict__ bb,
                       const float* __restrict__ gamma4, const float* __restrict__ beta4,
                       float* __restrict__ out, int G, float invN) {
    __shared__ float p[PAD];
    int g = blockIdx.x;
    if (threadIdx.x < PAD) {
        int c = threadIdx.x;
        float val = 0.f;
        if (c < DIM) {
            const float* s = g_sums + 4 * 64;
            float m = s[c] * invN;
            float var = s[PAD + c] * invN - m * m;
            float istd = rsqrtf(var + BN_EPS);
            float sc = gamma4[c] * istd;
            float sf = beta4[c] - m * sc;
            val = g_pooled[g * PAD + c] * sc + g_gcnt[g] * sf;
        }
        p[c] = val;
    }
    __syncthreads();
    int o = threadIdx.x;
    float acc = __ldg(bb + o);
#pragma unroll
    for (int i = 0; i < DIM; i++) acc += p[i] * __ldg(W + i * 256 + o);
    out[g * 256 + o] = fmaxf(acc, 0.f);
}

// ---------------- tiled SGEMM (f32x2 micro-kernel): C = act((A [+A2]) @ B + bias) ----------------
template <bool SUM2, bool RELU>
__global__ void k_gemm(const float* __restrict__ A, const float* __restrict__ A2,
                       const float* __restrict__ B, const float* __restrict__ bias,
                       float* __restrict__ C, int M, int N, int K) {
    const int BM = 64, BN = 64, BK = 16;
    __shared__ float As[BM][BK + 1];
    __shared__ float Bs[BK][BN];
    int tx = threadIdx.x % 16, ty = threadIdx.x / 16;
    int row0 = blockIdx.y * BM, col0 = blockIdx.x * BN;
    u64 acc2[4][2];
    u64 zero;
    PACK2(zero, 0.f, 0.f);
#pragma unroll
    for (int u = 0; u < 4; u++) {
        acc2[u][0] = zero;
        acc2[u][1] = zero;
    }
    for (int k0 = 0; k0 < K; k0 += BK) {
        for (int i = threadIdx.x; i < BM * BK; i += 256) {
            int r = i / BK, c = i % BK;
            float v = A[(size_t)(row0 + r) * K + k0 + c];
            if (SUM2) v += A2[(size_t)(row0 + r) * K + k0 + c];
            As[r][c] = v;
        }
        for (int i = threadIdx.x; i < BK * BN; i += 256) {
            int r = i / BN, c = i % BN;
            Bs[r][c] = B[(size_t)(k0 + r) * N + col0 + c];
        }
        __syncthreads();
#pragma unroll
        for (int k = 0; k < BK; k++) {
            u64 b0 = *(const u64*)&Bs[k][tx * 4];
            u64 b1 = *(const u64*)&Bs[k][tx * 4 + 2];
#pragma unroll
            for (int u = 0; u < 4; u++) {
                float a = As[ty * 4 + u][k];
                u64 ap;
                PACK2(ap, a, a);
                FMA2(acc2[u][0], ap, b0, acc2[u][0]);
                FMA2(acc2[u][1], ap, b1, acc2[u][1]);
            }
        }
        __syncthreads();
    }
#pragma unroll
    for (int u = 0; u < 4; u++) {
        int r = row0 + ty * 4 + u;
#pragma unroll
        for (int w = 0; w < 2; w++) {
            float lo, hi;
            UNPACK2(lo, hi, acc2[u][w]);
            int cc = col0 + tx * 4 + 2 * w;
            float v0 = lo + bias[cc];
            float v1 = hi + bias[cc + 1];
            if (RELU) {
                v0 = fmaxf(v0, 0.f);
                v1 = fmaxf(v1, 0.f);
            }
            C[(size_t)r * N + cc] = v0;
            C[(size_t)r * N + cc + 1] = v1;
        }
    }
}

// ---------------- final projection ----------------
__global__ void k_out(const float* __restrict__ W, const float* __restrict__ b,
                      float* __restrict__ out, int G) {
    __shared__ float sW[512];
    for (int i = threadIdx.x; i < 512; i += blockDim.x) sW[i] = W[i];
    __syncthreads();
    int g = blockIdx.x * blockDim.x + threadIdx.x;
    if (g >= G) return;
    const float4* row = (const float4*)(g_c2 + (size_t)g * 256);
    float a0 = b[0], a1 = b[1];
#pragma unroll 8
    for (int i = 0; i < 64; i++) {
        float4 v = row[i];
        int o = i * 4;
        a0 += v.x * sW[2 * o + 0] + v.y * sW[2 * o + 2] + v.z * sW[2 * o + 4] + v.w * sW[2 * o + 6];
        a1 += v.x * sW[2 * o + 1] + v.y * sW[2 * o + 3] + v.z * sW[2 * o + 5] + v.w * sW[2 * o + 7];
    }
    out[g * 2 + 0] = a0;
    out[g * 2 + 1] = a1;
}

// ---------------- launch ----------------
extern "C" void kernel_launch(void* const* d_in, const int* in_sizes, int n_in,
                              void* d_out, int out_size) {
    const float* x_a = (const float*)d_in[0];
    const int* ei_a = (const int*)d_in[1];
    const int* batch_a = (const int*)d_in[2];
    const float* x_b = (const float*)d_in[3];
    const int* ei_b = (const int*)d_in[4];
    const int* batch_b = (const int*)d_in[5];
    const float* W1s = (const float*)d_in[6];
    const float* b1s = (const float*)d_in[7];
    const float* W2s = (const float*)d_in[8];
    const float* b2s = (const float*)d_in[9];
    const float* gammas = (const float*)d_in[10];
    const float* betas = (const float*)d_in[11];
    const float* fcxW = (const float*)d_in[12];
    const float* fcxb = (const float*)d_in[13];
    const float* fc1W = (const float*)d_in[14];
    const float* fc1b = (const float*)d_in[15];
    const float* fc2W = (const float*)d_in[16];
    const float* fc2b = (const float*)d_in[17];
    const float* outW = (const float*)d_in[18];
    const float* outb = (const float*)d_in[19];

    int N = in_sizes[0] / DIM;
    int E = in_sizes[1] / 2;
    int G = out_size / 2;
    float invN = 1.f / (float)N;
    int NB = (N + 511) / 512;
    int NPB = (N + 127) / 128;

    float* sums_ptr;
    float* ha_ptr;
    float* hb_ptr;
    float* c1_ptr;
    float* c2_ptr;
    float* partial_ptr;
    float* y0_ptr;
    float* y1_ptr;
    cudaGetSymbolAddress((void**)&sums_ptr, g_sums);
    cudaGetSymbolAddress((void**)&ha_ptr, g_ha);
    cudaGetSymbolAddress((void**)&hb_ptr, g_hb);
    cudaGetSymbolAddress((void**)&c1_ptr, g_c1);
    cudaGetSymbolAddress((void**)&c2_ptr, g_c2);
    cudaGetSymbolAddress((void**)&partial_ptr, g_partial);
    cudaGetSymbolAddress((void**)&y0_ptr, g_y0);
    cudaGetSymbolAddress((void**)&y1_ptr, g_y1);
    float* ybuf[2] = {y0_ptr, y1_ptr};

    for (int br = 0; br < 2; br++) {
        const float* x = br ? x_b : x_a;
        const int* ei = br ? ei_b : ei_a;
        const int* batch = br ? batch_b : batch_a;
        float* h = br ? hb_ptr : ha_ptr;

        k_init<<<2048, 256>>>(x, N);
        k_count<<<2048, 256>>>(ei + E, E);
        k_scan1<<<NB, 512>>>(N);
        k_scan2<<<1, 1024>>>(NB);
        k_scan3<<<NB, 512>>>(N);
        k_fill<<<2048, 256>>>(ei, ei + E, E);

        for (int l = 0; l < 5; l++) {
            const float* sumsP = (l == 0) ? nullptr : sums_ptr + (l - 1) * 64;
            const float* gP = (l == 0) ? nullptr : gammas + (l - 1) * DIM;
            const float* bP = (l == 0) ? nullptr : betas + (l - 1) * DIM;
            k_gmlp<<<NPB, 128>>>(ybuf[l & 1], ybuf[1 - (l & 1)],
                                 W1s + l * DIM * DIM, b1s + l * DIM,
                                 W2s + l * DIM * DIM, b2s + l * DIM,
                                 gP, bP, sumsP, partial_ptr, N, invN);
            k_reduce<<<64, 256>>>(sums_ptr + l * 64, NPB);
        }
        // after 5 layers (writes: l=0->buf1, 1->buf0, 2->buf1, 3->buf0, 4->buf1)
        k_pool<<<(N * 8 + 255) / 256, 256>>>(ybuf[1], batch, N);
        k_fcbr<<<G, 256>>>(fcxW, fcxb, gammas + 4 * DIM, betas + 4 * DIM, h, G, invN);
    }

    dim3 g1(1024 / 64, G / 64);
    k_gemm<true, true><<<g1, 256>>>(ha_ptr, hb_ptr, fc1W, fc1b, c1_ptr, G, 1024, 256);
    dim3 g2(256 / 64, G / 64);
    k_gemm<false, true><<<g2, 256>>>(c1_ptr, nullptr, fc2W, fc2b, c2_ptr, G, 256, 1024);
    k_out<<<(G + 255) / 256, 256>>>(outW, outb, (float*)d_out, G);
}

// round 6
// speedup vs baseline: 1.3493x; 1.3493x over previous
#include <cuda_runtime.h>

#define DIM 31
#define PAD 32
#define NMAX 500000
#define EMAX 2000000
#define GMAX 4096
#define BN_EPS 1e-5f
#define NPB_MAX 4096

typedef unsigned long long u64;

#define PACK2(d, lo, hi) \
    asm("mov.b64 %0, {%1, %2};" : "=l"(d) : "r"(__float_as_uint(lo)), "r"(__float_as_uint(hi)))
#define UNPACK2(lo, hi, s)                                  \
    do {                                                    \
        unsigned _l, _h;                                    \
        asm("mov.b64 {%0, %1}, %2;" : "=r"(_l), "=r"(_h) : "l"(s)); \
        lo = __uint_as_float(_l);                           \
        hi = __uint_as_float(_h);                           \
    } while (0)
#define FMA2(d, a, b, c) \
    asm("fma.rn.f32x2 %0, %1, %2, %3;" : "=l"(d) : "l"(a), "l"(b), "l"(c))

// ---------------- scratch ----------------
__device__ float g_y[(size_t)NMAX * PAD];     // node features
__device__ float g_agg[(size_t)NMAX * PAD];   // self + gathered neighbor sums
__device__ int   g_cnt[NMAX];
__device__ int   g_rowptr[NMAX + 1];
__device__ int   g_cursor[NMAX];
__device__ int   g_perm[EMAX];
__device__ float g_deg[NMAX];
__device__ int   g_bsums[1024];
__device__ float g_partial[(size_t)NPB_MAX * 64];  // per-block column stats
__device__ float g_sums[5 * 64];              // per-layer colsum (c) + sumsq (32+c)
__device__ float g_pooled[GMAX * PAD];
__device__ float g_gcnt[GMAX];
__device__ float g_ha[GMAX * 256];
__device__ float g_hb[GMAX * 256];
__device__ float g_c1[GMAX * 1024];
__device__ float g_c2[GMAX * 256];

// ---------------- init: pack x, zero cnt/pooled/gcnt ----------------
__global__ void k_init(const float* __restrict__ x, int N) {
    int stride = gridDim.x * blockDim.x;
    int tid0 = blockIdx.x * blockDim.x + threadIdx.x;
    int total = N * PAD;
    for (int t = tid0; t < total; t += stride) {
        int c = t & (PAD - 1);
        int i = t >> 5;
        g_y[t] = (c < DIM) ? x[i * DIM + c] : 0.f;
    }
    for (int t = tid0; t < N; t += stride) g_cnt[t] = 0;
    for (int t = tid0; t < GMAX * PAD; t += stride) g_pooled[t] = 0.f;
    for (int t = tid0; t < GMAX; t += stride) g_gcnt[t] = 0.f;
}

// ---------------- CSR build ----------------
__global__ void k_count(const int* __restrict__ dst, int E) {
    for (int e = blockIdx.x * blockDim.x + threadIdx.x; e < E;
         e += gridDim.x * blockDim.x)
        atomicAdd(&g_cnt[__ldg(dst + e)], 1);
}

__global__ void k_scan1(int N) {
    __shared__ int s[512];
    int i = blockIdx.x * 512 + threadIdx.x;
    s[threadIdx.x] = (i < N) ? g_cnt[i] : 0;
    __syncthreads();
    for (int o = 256; o > 0; o >>= 1) {
        if (threadIdx.x < o) s[threadIdx.x] += s[threadIdx.x + o];
        __syncthreads();
    }
    if (threadIdx.x == 0) g_bsums[blockIdx.x] = s[0];
}

__global__ void k_scan2(int NB) {
    __shared__ int s[1024];
    int i = threadIdx.x;
    int v = (i < NB) ? g_bsums[i] : 0;
    s[i] = v;
    __syncthreads();
    for (int o = 1; o < 1024; o <<= 1) {
        int t = (i >= o) ? s[i - o] : 0;
        __syncthreads();
        s[i] += t;
        __syncthreads();
    }
    if (i < NB) g_bsums[i] = s[i] - v;  // exclusive
}

__global__ void k_scan3(int N) {
    __shared__ int s[512];
    int i = blockIdx.x * 512 + threadIdx.x;
    int c = (i < N) ? g_cnt[i] : 0;
    s[threadIdx.x] = c;
    __syncthreads();
    for (int o = 1; o < 512; o <<= 1) {
        int t = (threadIdx.x >= o) ? s[threadIdx.x - o] : 0;
        __syncthreads();
        s[threadIdx.x] += t;
        __syncthreads();
    }
    int ex = s[threadIdx.x] - c + g_bsums[blockIdx.x];
    if (i < N) {
        g_rowptr[i] = ex;
        g_cursor[i] = ex;
        g_deg[i] = (float)c;
        if (i == N - 1) g_rowptr[N] = ex + c;
    }
}

__global__ void k_fill(const int* __restrict__ src, const int* __restrict__ dst, int E) {
    for (int e = blockIdx.x * blockDim.x + threadIdx.x; e < E;
         e += gridDim.x * blockDim.x) {
        int d = __ldg(dst + e);
        int p = atomicAdd(&g_cursor[d], 1);
        g_perm[p] = __ldg(src + e);
    }
}

// ---------------- gather: agg[n] = y[n] + sum over in-neighbors of y[src] ----------------
__global__ void k_gather(int N) {
    int t = blockIdx.x * blockDim.x + threadIdx.x;
    int n = t >> 3, g = t & 7;
    if (n >= N) return;
    int beg = __ldg(g_rowptr + n), end = __ldg(g_rowptr + n + 1);
    float4 acc = ((const float4*)g_y)[(size_t)n * 8 + g];  // self row
    int p = beg;
    for (; p + 1 < end; p += 2) {
        int s0 = __ldg(g_perm + p);
        int s1 = __ldg(g_perm + p + 1);
        float4 v0 = *(const float4*)(g_y + (size_t)s0 * PAD + g * 4);
        float4 v1 = *(const float4*)(g_y + (size_t)s1 * PAD + g * 4);
        acc.x += v0.x + v1.x;
        acc.y += v0.y + v1.y;
        acc.z += v0.z + v1.z;
        acc.w += v0.w + v1.w;
    }
    if (p < end) {
        int s0 = __ldg(g_perm + p);
        float4 v0 = *(const float4*)(g_y + (size_t)s0 * PAD + g * 4);
        acc.x += v0.x;
        acc.y += v0.y;
        acc.z += v0.z;
        acc.w += v0.w;
    }
    ((float4*)g_agg)[(size_t)n * 8 + g] = acc;
}

// ---------------- MLP (f32x2 packed) with fused BN-affine input + block-local stats ----------------
__global__ void __launch_bounds__(128) k_mlp(const float* __restrict__ W1,
                                             const float* __restrict__ b1,
                                             const float* __restrict__ W2,
                                             const float* __restrict__ b2,
                                             const float* __restrict__ gammaP,
                                             const float* __restrict__ betaP,
                                             const float* __restrict__ sumsP,
                                             float* __restrict__ partial,
                                             int N, float invN) {
    __shared__ u64 sW1p[31 * 16], sW2p[31 * 16];
    __shared__ u64 sb1p[16], sb2p[16];
    __shared__ float ssc[32], ssf[32];
    __shared__ float sstat[4 * 64];

    // ---- load & pack weights ----
    for (int idx = threadIdx.x; idx < 31 * 16; idx += 128) {
        int i = idx >> 4, o = idx & 15;
        float lo = W1[i * 31 + 2 * o];
        float hi = (2 * o + 1 < 31) ? W1[i * 31 + 2 * o + 1] : 0.f;
        u64 p;
        PACK2(p, lo, hi);
        sW1p[idx] = p;
        lo = W2[i * 31 + 2 * o];
        hi = (2 * o + 1 < 31) ? W2[i * 31 + 2 * o + 1] : 0.f;
        PACK2(p, lo, hi);
        sW2p[idx] = p;
    }
    if (threadIdx.x < 16) {
        int o = threadIdx.x;
        float lo = b1[2 * o];
        float hi = (2 * o + 1 < 31) ? b1[2 * o + 1] : 0.f;
        u64 p;
        PACK2(p, lo, hi);
        sb1p[o] = p;
        lo = b2[2 * o];
        hi = (2 * o + 1 < 31) ? b2[2 * o + 1] : 0.f;
        PACK2(p, lo, hi);
        sb2p[o] = p;
    }
    if (threadIdx.x < 32) {
        int c = threadIdx.x;
        float sc = 0.f, sf = 0.f;
        if (c < DIM) {
            sc = 1.f;
            if (sumsP) {
                float m = sumsP[c] * invN;
                float var = sumsP[PAD + c] * invN - m * m;
                float istd = rsqrtf(var + BN_EPS);
                sc = gammaP[c] * istd;
                sf = betaP[c] - m * sc;
            }
        }
        ssc[c] = sc;
        ssf[c] = sf;
    }
    __syncthreads();

    int n = blockIdx.x * 128 + threadIdx.x;
    bool act = n < N;
    int nc = act ? n : (N - 1);  // clamp for safe reads; results masked below

    // ---- load agg row, apply previous-layer BN affine, pack ----
    u64 hpk[16];
    {
        const float4* ar = (const float4*)(g_agg + (size_t)nc * PAD);
        float dp1 = g_deg[nc] + 1.f;
#pragma unroll
        for (int g = 0; g < 8; g++) {
            float4 s = ar[g];
            int c = 4 * g;
            float h0 = ssc[c + 0] * s.x + dp1 * ssf[c + 0];
            float h1 = ssc[c + 1] * s.y + dp1 * ssf[c + 1];
            float h2 = ssc[c + 2] * s.z + dp1 * ssf[c + 2];
            float h3 = ssc[c + 3] * s.w + dp1 * ssf[c + 3];
            PACK2(hpk[2 * g + 0], h0, h1);
            PACK2(hpk[2 * g + 1], h2, h3);
        }
    }

    // ---- layer 1 ----
    u64 acc2[16];
#pragma unroll
    for (int o = 0; o < 16; o++) acc2[o] = sb1p[o];
#pragma unroll
    for (int ip = 0; ip < 16; ip++) {
        float x0, x1;
        UNPACK2(x0, x1, hpk[ip]);
        u64 xp;
        PACK2(xp, x0, x0);
        const u64* wr = sW1p + (2 * ip) * 16;
#pragma unroll
        for (int o = 0; o < 16; o++) FMA2(acc2[o], xp, wr[o], acc2[o]);
        if (ip < 15) {
            PACK2(xp, x1, x1);
            wr = sW1p + (2 * ip + 1) * 16;
#pragma unroll
            for (int o = 0; o < 16; o++) FMA2(acc2[o], xp, wr[o], acc2[o]);
        }
    }
    // relu hidden back into hpk (packed)
#pragma unroll
    for (int o = 0; o < 16; o++) {
        float lo, hi;
        UNPACK2(lo, hi, acc2[o]);
        PACK2(hpk[o], fmaxf(lo, 0.f), fmaxf(hi, 0.f));
    }

    // ---- layer 2 ----
#pragma unroll
    for (int o = 0; o < 16; o++) acc2[o] = sb2p[o];
#pragma unroll
    for (int ip = 0; ip < 16; ip++) {
        float x0, x1;
        UNPACK2(x0, x1, hpk[ip]);
        u64 xp;
        PACK2(xp, x0, x0);
        const u64* wr = sW2p + (2 * ip) * 16;
#pragma unroll
        for (int o = 0; o < 16; o++) FMA2(acc2[o], xp, wr[o], acc2[o]);
        if (ip < 15) {
            PACK2(xp, x1, x1);
            wr = sW2p + (2 * ip + 1) * 16;
#pragma unroll
            for (int o = 0; o < 16; o++) FMA2(acc2[o], xp, wr[o], acc2[o]);
        }
    }

    // ---- relu + mask + store + column stats (pair at a time, bounded liveness) ----
    int wid = threadIdx.x >> 5, lane = threadIdx.x & 31;
    float am = act ? 1.f : 0.f;
    float4* outp = (float4*)(g_y + (size_t)n * PAD);
    float prev0 = 0.f, prev1 = 0.f;
#pragma unroll
    for (int o = 0; o < 16; o++) {
        float lo, hi;
        UNPACK2(lo, hi, acc2[o]);
        lo = fmaxf(lo, 0.f) * am;
        hi = fmaxf(hi, 0.f) * am;
        float s0 = lo, q0 = lo * lo, s1 = hi, q1 = hi * hi;
#pragma unroll
        for (int off = 16; off > 0; off >>= 1) {
            s0 += __shfl_xor_sync(0xffffffffu, s0, off);
            q0 += __shfl_xor_sync(0xffffffffu, q0, off);
            s1 += __shfl_xor_sync(0xffffffffu, s1, off);
            q1 += __shfl_xor_sync(0xffffffffu, q1, off);
        }
        if (lane == 0) {
            sstat[wid * 64 + 2 * o + 0] = s0;
            sstat[wid * 64 + 32 + 2 * o + 0] = q0;
            sstat[wid * 64 + 2 * o + 1] = s1;
            sstat[wid * 64 + 32 + 2 * o + 1] = q1;
        }
        if ((o & 1) == 0) {
            prev0 = lo;
            prev1 = hi;
        } else if (act) {
            outp[o >> 1] = make_float4(prev0, prev1, lo, hi);
        }
    }
    __syncthreads();
    if (threadIdx.x < 64) {
        float t = sstat[threadIdx.x] + sstat[64 + threadIdx.x] +
                  sstat[128 + threadIdx.x] + sstat[192 + threadIdx.x];
        partial[(size_t)blockIdx.x * 64 + threadIdx.x] = t;
    }
}

// ---------------- reduce per-block partials into g_sums[l*64..] ----------------
__global__ void k_reduce(float* __restrict__ out, int NPB) {
    int slot = blockIdx.x;  // 64 blocks
    float s = 0.f;
    for (int i = threadIdx.x; i < NPB; i += blockDim.x)
        s += g_partial[(size_t)i * 64 + slot];
#pragma unroll
    for (int o = 16; o > 0; o >>= 1) s += __shfl_xor_sync(0xffffffffu, s, o);
    __shared__ float sh[8];
    if ((threadIdx.x & 31) == 0) sh[threadIdx.x >> 5] = s;
    __syncthreads();
    if (threadIdx.x == 0) {
        float t = 0.f;
#pragma unroll
        for (int w = 0; w < 8; w++) t += sh[w];
        out[slot] = t;
    }
}

// ---------------- pooling: raw sums + counts, warp-aggregated ----------------
__global__ void k_pool(const int* __restrict__ batch, int N) {
    int t = blockIdx.x * blockDim.x + threadIdx.x;
    int n = t >> 3, g = t & 7, lane = threadIdx.x & 31;
    int b = -1;
    float4 v = make_float4(0.f, 0.f, 0.f, 0.f);
    if (n < N) {
        b = __ldg(batch + n);
        v = ((const float4*)g_y)[(size_t)n * 8 + g];
    }
    int b1 = __shfl_xor_sync(0xffffffffu, b, 8);
    int b2 = __shfl_xor_sync(0xffffffffu, b, 16);
    int b3 = __shfl_xor_sync(0xffffffffu, b, 24);
    bool allsame = (b == b1) && (b == b2) && (b == b3);
    if (allsame) {
        v.x += __shfl_xor_sync(0xffffffffu, v.x, 8);
        v.y += __shfl_xor_sync(0xffffffffu, v.y, 8);
        v.z += __shfl_xor_sync(0xffffffffu, v.z, 8);
        v.w += __shfl_xor_sync(0xffffffffu, v.w, 8);
        v.x += __shfl_xor_sync(0xffffffffu, v.x, 16);
        v.y += __shfl_xor_sync(0xffffffffu, v.y, 16);
        v.z += __shfl_xor_sync(0xffffffffu, v.z, 16);
        v.w += __shfl_xor_sync(0xffffffffu, v.w, 16);
        if (b >= 0 && lane < 8) {
            float* p = g_pooled + (size_t)b * PAD + g * 4;
            atomicAdd(p + 0, v.x);
            atomicAdd(p + 1, v.y);
            atomicAdd(p + 2, v.z);
            if (g < 7) atomicAdd(p + 3, v.w);
            if (lane == 0) atomicAdd(&g_gcnt[b], 4.f);
        }
    } else {
        if (b >= 0) {
            float* p = g_pooled + (size_t)b * PAD + g * 4;
            atomicAdd(p + 0, v.x);
            atomicAdd(p + 1, v.y);
            atomicAdd(p + 2, v.z);
            if (g < 7) atomicAdd(p + 3, v.w);
            if (g == 0) atomicAdd(&g_gcnt[b], 1.f);
        }
    }
}

// ---------------- per-graph fc with layer-4 BN affine applied to pooled ----------------
__global__ void k_fcbr(const float* __restrict__ W, const float* __restrict__ bb,
                       const float* __restrict__ gamma4, const float* __restrict__ beta4,
                       float* __restrict__ out, int G, float invN) {
    __shared__ float p[PAD];
    int g = blockIdx.x;
    if (threadIdx.x < PAD) {
        int c = threadIdx.x;
        float val = 0.f;
        if (c < DIM) {
            const float* s = g_sums + 4 * 64;
            float m = s[c] * invN;
            float var = s[PAD + c] * invN - m * m;
            float istd = rsqrtf(var + BN_EPS);
            float sc = gamma4[c] * istd;
            float sf = beta4[c] - m * sc;
            val = g_pooled[g * PAD + c] * sc + g_gcnt[g] * sf;
        }
        p[c] = val;
    }
    __syncthreads();
    int o = threadIdx.x;
    float acc = __ldg(bb + o);
#pragma unroll
    for (int i = 0; i < DIM; i++) acc += p[i] * __ldg(W + i * 256 + o);
    out[g * 256 + o] = fmaxf(acc, 0.f);
}

// ---------------- tiled SGEMM (f32x2 micro-kernel): C = act((A [+A2]) @ B + bias) ----------------
template <bool SUM2, bool RELU>
__global__ void k_gemm(const float* __restrict__ A, const float* __restrict__ A2,
                       const float* __restrict__ B, const float* __restrict__ bias,
                       float* __restrict__ C, int M, int N, int K) {
    const int BM = 64, BN = 64, BK = 16;
    __shared__ float As[BM][BK + 1];
    __shared__ float Bs[BK][BN];
    int tx = threadIdx.x % 16, ty = threadIdx.x / 16;
    int row0 = blockIdx.y * BM, col0 = blockIdx.x * BN;
    u64 acc2[4][2];
    u64 zero;
    PACK2(zero, 0.f, 0.f);
#pragma unroll
    for (int u = 0; u < 4; u++) {
        acc2[u][0] = zero;
        acc2[u][1] = zero;
    }
    for (int k0 = 0; k0 < K; k0 += BK) {
        for (int i = threadIdx.x; i < BM * BK; i += 256) {
            int r = i / BK, c = i % BK;
            float v = A[(size_t)(row0 + r) * K + k0 + c];
            if (SUM2) v += A2[(size_t)(row0 + r) * K + k0 + c];
            As[r][c] = v;
        }
        for (int i = threadIdx.x; i < BK * BN; i += 256) {
            int r = i / BN, c = i % BN;
            Bs[r][c] = B[(size_t)(k0 + r) * N + col0 + c];
        }
        __syncthreads();
#pragma unroll
        for (int k = 0; k < BK; k++) {
            u64 b0 = *(const u64*)&Bs[k][tx * 4];
            u64 b1 = *(const u64*)&Bs[k][tx * 4 + 2];
#pragma unroll
            for (int u = 0; u < 4; u++) {
                float a = As[ty * 4 + u][k];
                u64 ap;
                PACK2(ap, a, a);
                FMA2(acc2[u][0], ap, b0, acc2[u][0]);
                FMA2(acc2[u][1], ap, b1, acc2[u][1]);
            }
        }
        __syncthreads();
    }
#pragma unroll
    for (int u = 0; u < 4; u++) {
        int r = row0 + ty * 4 + u;
#pragma unroll
        for (int w = 0; w < 2; w++) {
            float lo, hi;
            UNPACK2(lo, hi, acc2[u][w]);
            int cc = col0 + tx * 4 + 2 * w;
            float v0 = lo + bias[cc];
            float v1 = hi + bias[cc + 1];
            if (RELU) {
                v0 = fmaxf(v0, 0.f);
                v1 = fmaxf(v1, 0.f);
            }
            C[(size_t)r * N + cc] = v0;
            C[(size_t)r * N + cc + 1] = v1;
        }
    }
}

// ---------------- final projection ----------------
__global__ void k_out(const float* __restrict__ W, const float* __restrict__ b,
                      float* __restrict__ out, int G) {
    __shared__ float sW[512];
    for (int i = threadIdx.x; i < 512; i += blockDim.x) sW[i] = W[i];
    __syncthreads();
    int g = blockIdx.x * blockDim.x + threadIdx.x;
    if (g >= G) return;
    const float4* row = (const float4*)(g_c2 + (size_t)g * 256);
    float a0 = b[0], a1 = b[1];
#pragma unroll 8
    for (int i = 0; i < 64; i++) {
        float4 v = row[i];
        int o = i * 4;
        a0 += v.x * sW[2 * o + 0] + v.y * sW[2 * o + 2] + v.z * sW[2 * o + 4] + v.w * sW[2 * o + 6];
        a1 += v.x * sW[2 * o + 1] + v.y * sW[2 * o + 3] + v.z * sW[2 * o + 5] + v.w * sW[2 * o + 7];
    }
    out[g * 2 + 0] = a0;
    out[g * 2 + 1] = a1;
}

// ---------------- launch ----------------
extern "C" void kernel_launch(void* const* d_in, const int* in_sizes, int n_in,
                              void* d_out, int out_size) {
    const float* x_a = (const float*)d_in[0];
    const int* ei_a = (const int*)d_in[1];
    const int* batch_a = (const int*)d_in[2];
    const float* x_b = (const float*)d_in[3];
    const int* ei_b = (const int*)d_in[4];
    const int* batch_b = (const int*)d_in[5];
    const float* W1s = (const float*)d_in[6];
    const float* b1s = (const float*)d_in[7];
    const float* W2s = (const float*)d_in[8];
    const float* b2s = (const float*)d_in[9];
    const float* gammas = (const float*)d_in[10];
    const float* betas = (const float*)d_in[11];
    const float* fcxW = (const float*)d_in[12];
    const float* fcxb = (const float*)d_in[13];
    const float* fc1W = (const float*)d_in[14];
    const float* fc1b = (const float*)d_in[15];
    const float* fc2W = (const float*)d_in[16];
    const float* fc2b = (const float*)d_in[17];
    const float* outW = (const float*)d_in[18];
    const float* outb = (const float*)d_in[19];

    int N = in_sizes[0] / DIM;
    int E = in_sizes[1] / 2;
    int G = out_size / 2;
    float invN = 1.f / (float)N;
    int NB = (N + 511) / 512;
    int NPB = (N + 127) / 128;

    float* sums_ptr;
    float* ha_ptr;
    float* hb_ptr;
    float* c1_ptr;
    float* c2_ptr;
    float* partial_ptr;
    cudaGetSymbolAddress((void**)&sums_ptr, g_sums);
    cudaGetSymbolAddress((void**)&ha_ptr, g_ha);
    cudaGetSymbolAddress((void**)&hb_ptr, g_hb);
    cudaGetSymbolAddress((void**)&c1_ptr, g_c1);
    cudaGetSymbolAddress((void**)&c2_ptr, g_c2);
    cudaGetSymbolAddress((void**)&partial_ptr, g_partial);

    for (int br = 0; br < 2; br++) {
        const float* x = br ? x_b : x_a;
        const int* ei = br ? ei_b : ei_a;
        const int* batch = br ? batch_b : batch_a;
        float* h = br ? hb_ptr : ha_ptr;

        k_init<<<2048, 256>>>(x, N);
        k_count<<<2048, 256>>>(ei + E, E);
        k_scan1<<<NB, 512>>>(N);
        k_scan2<<<1, 1024>>>(NB);
        k_scan3<<<NB, 512>>>(N);
        k_fill<<<2048, 256>>>(ei, ei + E, E);

        for (int l = 0; l < 5; l++) {
            k_gather<<<(N * 8 + 255) / 256, 256>>>(N);
            const float* sumsP = (l == 0) ? nullptr : sums_ptr + (l - 1) * 64;
            const float* gP = (l == 0) ? nullptr : gammas + (l - 1) * DIM;
            const float* bP = (l == 0) ? nullptr : betas + (l - 1) * DIM;
            k_mlp<<<NPB, 128>>>(W1s + l * DIM * DIM, b1s + l * DIM,
                                W2s + l * DIM * DIM, b2s + l * DIM,
                                gP, bP, sumsP, partial_ptr, N, invN);
            k_reduce<<<64, 256>>>(sums_ptr + l * 64, NPB);
        }
        k_pool<<<(N * 8 + 255) / 256, 256>>>(batch, N);
        k_fcbr<<<G, 256>>>(fcxW, fcxb, gammas + 4 * DIM, betas + 4 * DIM, h, G, invN);
    }

    dim3 g1(1024 / 64, G / 64);
    k_gemm<true, true><<<g1, 256>>>(ha_ptr, hb_ptr, fc1W, fc1b, c1_ptr, G, 1024, 256);
    dim3 g2(256 / 64, G / 64);
    k_gemm<false, true><<<g2, 256>>>(c1_ptr, nullptr, fc2W, fc2b, c2_ptr, G, 256, 1024);
    k_out<<<(G + 255) / 256, 256>>>(outW, outb, (float*)d_out, G);
}

// round 7
// speedup vs baseline: 1.3883x; 1.0289x over previous
#include <cuda_runtime.h>

#define DIM 31
#define PAD 32
#define NMAX 500000
#define EMAX 2000000
#define GMAX 4096
#define BN_EPS 1e-5f
#define NPB_MAX 8192

typedef unsigned long long u64;

#define PACK2(d, lo, hi) \
    asm("mov.b64 %0, {%1, %2};" : "=l"(d) : "r"(__float_as_uint(lo)), "r"(__float_as_uint(hi)))
#define UNPACK2(lo, hi, s)                                  \
    do {                                                    \
        unsigned _l, _h;                                    \
        asm("mov.b64 {%0, %1}, %2;" : "=r"(_l), "=r"(_h) : "l"(s)); \
        lo = __uint_as_float(_l);                           \
        hi = __uint_as_float(_h);                           \
    } while (0)
#define FMA2(d, a, b, c) \
    asm("fma.rn.f32x2 %0, %1, %2, %3;" : "=l"(d) : "l"(a), "l"(b), "l"(c))

// ---------------- scratch (both branches concatenated: 2N nodes) ----------------
__device__ float g_y[(size_t)2 * NMAX * PAD];
__device__ float g_agg[(size_t)2 * NMAX * PAD];
__device__ int   g_cnt[2 * NMAX];
__device__ int   g_rowptr[2 * NMAX];
__device__ int   g_cursor[2 * NMAX];
__device__ int   g_perm[2 * EMAX];
__device__ float g_deg[2 * NMAX];
__device__ int   g_total;
__device__ float g_partial[(size_t)NPB_MAX * 64];
__device__ float g_sums[5 * 128];             // per layer: [A colsum32|A sumsq32|B colsum32|B sumsq32]
__device__ float g_pooled[2 * GMAX * PAD];
__device__ float g_gcnt[2 * GMAX];
__device__ float g_ha[(size_t)2 * GMAX * 256];
__device__ float g_c1[(size_t)GMAX * 1024];
__device__ float g_c2[GMAX * 256];

// ---------------- zero + pack both branches ----------------
__global__ void k_zero(const float* __restrict__ xa, const float* __restrict__ xb,
                       int N, int G) {
    int stride = gridDim.x * blockDim.x;
    int tid0 = blockIdx.x * blockDim.x + threadIdx.x;
    int total = N * PAD;
    for (int t = tid0; t < total; t += stride) {
        int c = t & (PAD - 1);
        int i = t >> 5;
        float va = (c < DIM) ? xa[i * DIM + c] : 0.f;
        float vb = (c < DIM) ? xb[i * DIM + c] : 0.f;
        g_y[t] = va;
        g_y[(size_t)N * PAD + t] = vb;
    }
    for (int t = tid0; t < 2 * N; t += stride) g_cnt[t] = 0;
    for (int t = tid0; t < 2 * G * PAD; t += stride) g_pooled[t] = 0.f;
    for (int t = tid0; t < 2 * G; t += stride) g_gcnt[t] = 0.f;
    if (tid0 == 0) g_total = 0;
}

// ---------------- count in-degree for both branches ----------------
__global__ void k_count(const int* __restrict__ dsta, const int* __restrict__ dstb,
                        int E, int N) {
    for (int e = blockIdx.x * blockDim.x + threadIdx.x; e < 2 * E;
         e += gridDim.x * blockDim.x) {
        int d = (e < E) ? __ldg(dsta + e) : (__ldg(dstb + e - E) + N);
        atomicAdd(&g_cnt[d], 1);
    }
}

// ---------------- scan-free segment assignment ----------------
__global__ void k_assign(int NN) {
    __shared__ int s[512];
    __shared__ int sbase;
    int i = blockIdx.x * 512 + threadIdx.x;
    int c = (i < NN) ? g_cnt[i] : 0;
    s[threadIdx.x] = c;
    __syncthreads();
    for (int o = 1; o < 512; o <<= 1) {
        int t = (threadIdx.x >= o) ? s[threadIdx.x - o] : 0;
        __syncthreads();
        s[threadIdx.x] += t;
        __syncthreads();
    }
    if (threadIdx.x == 511) sbase = atomicAdd(&g_total, s[511]);
    __syncthreads();
    int ex = s[threadIdx.x] - c + sbase;
    if (i < NN) {
        g_rowptr[i] = ex;
        g_cursor[i] = ex;
        g_deg[i] = (float)c;
    }
}

// ---------------- fill CSR for both branches ----------------
__global__ void k_fill(const int* __restrict__ srca, const int* __restrict__ dsta,
                       const int* __restrict__ srcb, const int* __restrict__ dstb,
                       int E, int N) {
    for (int e = blockIdx.x * blockDim.x + threadIdx.x; e < 2 * E;
         e += gridDim.x * blockDim.x) {
        int d, s;
        if (e < E) {
            d = __ldg(dsta + e);
            s = __ldg(srca + e);
        } else {
            d = __ldg(dstb + e - E) + N;
            s = __ldg(srcb + e - E) + N;
        }
        int p = atomicAdd(&g_cursor[d], 1);
        g_perm[p] = s;
    }
}

// ---------------- gather: agg[n] = y[n] + sum of in-neighbor rows ----------------
__global__ void k_gather(int NN) {
    int t = blockIdx.x * blockDim.x + threadIdx.x;
    int n = t >> 3, g = t & 7;
    if (n >= NN) return;
    int beg = __ldg(g_rowptr + n);
    int end = beg + __ldg(g_cnt + n);
    float4 acc = ((const float4*)g_y)[(size_t)n * 8 + g];
    int p = beg;
    for (; p + 1 < end; p += 2) {
        int s0 = __ldg(g_perm + p);
        int s1 = __ldg(g_perm + p + 1);
        float4 v0 = *(const float4*)(g_y + (size_t)s0 * PAD + g * 4);
        float4 v1 = *(const float4*)(g_y + (size_t)s1 * PAD + g * 4);
        acc.x += v0.x + v1.x;
        acc.y += v0.y + v1.y;
        acc.z += v0.z + v1.z;
        acc.w += v0.w + v1.w;
    }
    if (p < end) {
        int s0 = __ldg(g_perm + p);
        float4 v0 = *(const float4*)(g_y + (size_t)s0 * PAD + g * 4);
        acc.x += v0.x;
        acc.y += v0.y;
        acc.z += v0.z;
        acc.w += v0.w;
    }
    ((float4*)g_agg)[(size_t)n * 8 + g] = acc;
}

// ---------------- MLP (f32x2) + per-branch BN affine + stats + optional fused pool ----------------
__global__ void __launch_bounds__(128) k_mlp(const float* __restrict__ W1,
                                             const float* __restrict__ b1,
                                             const float* __restrict__ W2,
                                             const float* __restrict__ b2,
                                             const float* __restrict__ gammaP,
                                             const float* __restrict__ betaP,
                                             const float* __restrict__ sumsPA,
                                             const float* __restrict__ sumsPB,
                                             float* __restrict__ partial,
                                             const int* __restrict__ batchA,
                                             const int* __restrict__ batchB,
                                             int N, int G, int NPBh, float invN) {
    __shared__ u64 sW1p[31 * 16], sW2p[31 * 16];
    __shared__ u64 sb1p[16], sb2p[16];
    __shared__ float ssc[32], ssf[32];
    __shared__ float sstat[4 * 64];

    bool brB = blockIdx.x >= NPBh;
    const float* sumsP = brB ? sumsPB : sumsPA;

    for (int idx = threadIdx.x; idx < 31 * 16; idx += 128) {
        int i = idx >> 4, o = idx & 15;
        float lo = W1[i * 31 + 2 * o];
        float hi = (2 * o + 1 < 31) ? W1[i * 31 + 2 * o + 1] : 0.f;
        u64 p;
        PACK2(p, lo, hi);
        sW1p[idx] = p;
        lo = W2[i * 31 + 2 * o];
        hi = (2 * o + 1 < 31) ? W2[i * 31 + 2 * o + 1] : 0.f;
        PACK2(p, lo, hi);
        sW2p[idx] = p;
    }
    if (threadIdx.x < 16) {
        int o = threadIdx.x;
        float lo = b1[2 * o];
        float hi = (2 * o + 1 < 31) ? b1[2 * o + 1] : 0.f;
        u64 p;
        PACK2(p, lo, hi);
        sb1p[o] = p;
        lo = b2[2 * o];
        hi = (2 * o + 1 < 31) ? b2[2 * o + 1] : 0.f;
        PACK2(p, lo, hi);
        sb2p[o] = p;
    }
    if (threadIdx.x < 32) {
        int c = threadIdx.x;
        float sc = 0.f, sf = 0.f;
        if (c < DIM) {
            sc = 1.f;
            if (sumsP) {
                float m = sumsP[c] * invN;
                float var = sumsP[PAD + c] * invN - m * m;
                float istd = rsqrtf(var + BN_EPS);
                sc = gammaP[c] * istd;
                sf = betaP[c] - m * sc;
            }
        }
        ssc[c] = sc;
        ssf[c] = sf;
    }
    __syncthreads();

    int ln = (blockIdx.x - (brB ? NPBh : 0)) * 128 + threadIdx.x;
    bool act = ln < N;
    int lnc = act ? ln : (N - 1);
    int n = ln + (brB ? N : 0);
    int nc = lnc + (brB ? N : 0);

    // pooling setup (only when batch pointers given: layer 4)
    bool doPool = (batchA != nullptr);
    int b = -1;
    if (doPool && act) b = brB ? (__ldg(batchB + lnc) + G) : __ldg(batchA + lnc);
    unsigned actmask = __ballot_sync(0xffffffffu, act);
    int b0 = __shfl_sync(0xffffffffu, b, 0);
    bool uniform = doPool && (b0 >= 0) &&
                   __all_sync(0xffffffffu, (b == b0) || (b < 0));
    int cntAct = __popc(actmask);

    // ---- load agg row, apply previous-layer BN affine, pack ----
    u64 hpk[16];
    {
        const float4* ar = (const float4*)(g_agg + (size_t)nc * PAD);
        float dp1 = g_deg[nc] + 1.f;
#pragma unroll
        for (int g = 0; g < 8; g++) {
            float4 s = ar[g];
            int c = 4 * g;
            float h0 = ssc[c + 0] * s.x + dp1 * ssf[c + 0];
            float h1 = ssc[c + 1] * s.y + dp1 * ssf[c + 1];
            float h2 = ssc[c + 2] * s.z + dp1 * ssf[c + 2];
            float h3 = ssc[c + 3] * s.w + dp1 * ssf[c + 3];
            PACK2(hpk[2 * g + 0], h0, h1);
            PACK2(hpk[2 * g + 1], h2, h3);
        }
    }

    // ---- layer 1 ----
    u64 acc2[16];
#pragma unroll
    for (int o = 0; o < 16; o++) acc2[o] = sb1p[o];
#pragma unroll
    for (int ip = 0; ip < 16; ip++) {
        float x0, x1;
        UNPACK2(x0, x1, hpk[ip]);
        u64 xp;
        PACK2(xp, x0, x0);
        const u64* wr = sW1p + (2 * ip) * 16;
#pragma unroll
        for (int o = 0; o < 16; o++) FMA2(acc2[o], xp, wr[o], acc2[o]);
        if (ip < 15) {
            PACK2(xp, x1, x1);
            wr = sW1p + (2 * ip + 1) * 16;
#pragma unroll
            for (int o = 0; o < 16; o++) FMA2(acc2[o], xp, wr[o], acc2[o]);
        }
    }
#pragma unroll
    for (int o = 0; o < 16; o++) {
        float lo, hi;
        UNPACK2(lo, hi, acc2[o]);
        PACK2(hpk[o], fmaxf(lo, 0.f), fmaxf(hi, 0.f));
    }

    // ---- layer 2 ----
#pragma unroll
    for (int o = 0; o < 16; o++) acc2[o] = sb2p[o];
#pragma unroll
    for (int ip = 0; ip < 16; ip++) {
        float x0, x1;
        UNPACK2(x0, x1, hpk[ip]);
        u64 xp;
        PACK2(xp, x0, x0);
        const u64* wr = sW2p + (2 * ip) * 16;
#pragma unroll
        for (int o = 0; o < 16; o++) FMA2(acc2[o], xp, wr[o], acc2[o]);
        if (ip < 15) {
            PACK2(xp, x1, x1);
            wr = sW2p + (2 * ip + 1) * 16;
#pragma unroll
            for (int o = 0; o < 16; o++) FMA2(acc2[o], xp, wr[o], acc2[o]);
        }
    }

    // ---- relu + mask + store + stats (+fused pool) ----
    int wid = threadIdx.x >> 5, lane = threadIdx.x & 31;
    float am = act ? 1.f : 0.f;
    float4* outp = (float4*)(g_y + (size_t)n * PAD);
    float prev0 = 0.f, prev1 = 0.f;
#pragma unroll
    for (int o = 0; o < 16; o++) {
        float lo, hi;
        UNPACK2(lo, hi, acc2[o]);
        lo = fmaxf(lo, 0.f) * am;
        hi = fmaxf(hi, 0.f) * am;
        float s0 = lo, q0 = lo * lo, s1 = hi, q1 = hi * hi;
#pragma unroll
        for (int off = 16; off > 0; off >>= 1) {
            s0 += __shfl_xor_sync(0xffffffffu, s0, off);
            q0 += __shfl_xor_sync(0xffffffffu, q0, off);
            s1 += __shfl_xor_sync(0xffffffffu, s1, off);
            q1 += __shfl_xor_sync(0xffffffffu, q1, off);
        }
        if (lane == 0) {
            sstat[wid * 64 + 2 * o + 0] = s0;
            sstat[wid * 64 + 32 + 2 * o + 0] = q0;
            sstat[wid * 64 + 2 * o + 1] = s1;
            sstat[wid * 64 + 32 + 2 * o + 1] = q1;
        }
        if (doPool) {
            if (uniform) {
                if (lane == 0) {
                    atomicAdd(&g_pooled[(size_t)b0 * PAD + 2 * o], s0);
                    if (2 * o + 1 < DIM)
                        atomicAdd(&g_pooled[(size_t)b0 * PAD + 2 * o + 1], s1);
                }
            } else if (act) {
                atomicAdd(&g_pooled[(size_t)b * PAD + 2 * o], lo);
                if (2 * o + 1 < DIM)
                    atomicAdd(&g_pooled[(size_t)b * PAD + 2 * o + 1], hi);
            }
        }
        if ((o & 1) == 0) {
            prev0 = lo;
            prev1 = hi;
        } else if (act) {
            outp[o >> 1] = make_float4(prev0, prev1, lo, hi);
        }
    }
    if (doPool) {
        if (uniform) {
            if (lane == 0) atomicAdd(&g_gcnt[b0], (float)cntAct);
        } else if (act) {
            atomicAdd(&g_gcnt[b], 1.f);
        }
    }
    __syncthreads();
    if (threadIdx.x < 64) {
        float t = sstat[threadIdx.x] + sstat[64 + threadIdx.x] +
                  sstat[128 + threadIdx.x] + sstat[192 + threadIdx.x];
        partial[(size_t)blockIdx.x * 64 + threadIdx.x] = t;
    }
}

// ---------------- reduce partials: 128 slots (A:0-63, B:64-127) ----------------
__global__ void k_reduce(float* __restrict__ out, int NPBh) {
    int blk = blockIdx.x;  // 128 blocks
    int slot = blk & 63;
    int start = (blk >= 64) ? NPBh : 0;
    float s = 0.f;
    for (int i = threadIdx.x; i < NPBh; i += blockDim.x)
        s += g_partial[(size_t)(start + i) * 64 + slot];
#pragma unroll
    for (int o = 16; o > 0; o >>= 1) s += __shfl_xor_sync(0xffffffffu, s, o);
    __shared__ float sh[8];
    if ((threadIdx.x & 31) == 0) sh[threadIdx.x >> 5] = s;
    __syncthreads();
    if (threadIdx.x == 0) {
        float t = 0.f;
#pragma unroll
        for (int w = 0; w < 8; w++) t += sh[w];
        out[blk] = t;
    }
}

// ---------------- per-graph fc with per-branch layer-4 BN affine ----------------
__global__ void k_fcbr(const float* __restrict__ W, const float* __restrict__ bb,
                       const float* __restrict__ gamma4, const float* __restrict__ beta4,
                       float* __restrict__ out, int G, float invN) {
    __shared__ float p[PAD];
    int g = blockIdx.x;  // 0..2G-1
    if (threadIdx.x < PAD) {
        int c = threadIdx.x;
        float val = 0.f;
        if (c < DIM) {
            const float* s = g_sums + 4 * 128 + ((g >= G) ? 64 : 0);
            float m = s[c] * invN;
            float var = s[PAD + c] * invN - m * m;
            float istd = rsqrtf(var + BN_EPS);
            float sc = gamma4[c] * istd;
            float sf = beta4[c] - m * sc;
            val = g_pooled[(size_t)g * PAD + c] * sc + g_gcnt[g] * sf;
        }
        p[c] = val;
    }
    __syncthreads();
    int o = threadIdx.x;
    float acc = __ldg(bb + o);
#pragma unroll
    for (int i = 0; i < DIM; i++) acc += p[i] * __ldg(W + i * 256 + o);
    out[(size_t)g * 256 + o] = fmaxf(acc, 0.f);
}

// ---------------- tiled SGEMM (f32x2): C = act((A [+A2]) @ B + bias) ----------------
template <bool SUM2, bool RELU>
__global__ void k_gemm(const float* __restrict__ A, const float* __restrict__ A2,
                       const float* __restrict__ B, const float* __restrict__ bias,
                       float* __restrict__ C, int M, int N, int K) {
    const int BM = 64, BN = 64, BK = 16;
    __shared__ float As[BM][BK + 1];
    __shared__ float Bs[BK][BN];
    int tx = threadIdx.x % 16, ty = threadIdx.x / 16;
    int row0 = blockIdx.y * BM, col0 = blockIdx.x * BN;
    u64 acc2[4][2];
    u64 zero;
    PACK2(zero, 0.f, 0.f);
#pragma unroll
    for (int u = 0; u < 4; u++) {
        acc2[u][0] = zero;
        acc2[u][1] = zero;
    }
    for (int k0 = 0; k0 < K; k0 += BK) {
        for (int i = threadIdx.x; i < BM * BK; i += 256) {
            int r = i / BK, c = i % BK;
            float v = A[(size_t)(row0 + r) * K + k0 + c];
            if (SUM2) v += A2[(size_t)(row0 + r) * K + k0 + c];
            As[r][c] = v;
        }
        for (int i = threadIdx.x; i < BK * BN; i += 256) {
            int r = i / BN, c = i % BN;
            Bs[r][c] = B[(size_t)(k0 + r) * N + col0 + c];
        }
        __syncthreads();
#pragma unroll
        for (int k = 0; k < BK; k++) {
            u64 b0 = *(const u64*)&Bs[k][tx * 4];
            u64 b1 = *(const u64*)&Bs[k][tx * 4 + 2];
#pragma unroll
            for (int u = 0; u < 4; u++) {
                float a = As[ty * 4 + u][k];
                u64 ap;
                PACK2(ap, a, a);
                FMA2(acc2[u][0], ap, b0, acc2[u][0]);
                FMA2(acc2[u][1], ap, b1, acc2[u][1]);
            }
        }
        __syncthreads();
    }
#pragma unroll
    for (int u = 0; u < 4; u++) {
        int r = row0 + ty * 4 + u;
#pragma unroll
        for (int w = 0; w < 2; w++) {
            float lo, hi;
            UNPACK2(lo, hi, acc2[u][w]);
            int cc = col0 + tx * 4 + 2 * w;
            float v0 = lo + bias[cc];
            float v1 = hi + bias[cc + 1];
            if (RELU) {
                v0 = fmaxf(v0, 0.f);
                v1 = fmaxf(v1, 0.f);
            }
            C[(size_t)r * N + cc] = v0;
            C[(size_t)r * N + cc + 1] = v1;
        }
    }
}

// ---------------- final projection ----------------
__global__ void k_out(const float* __restrict__ W, const float* __restrict__ b,
                      float* __restrict__ out, int G) {
    __shared__ float sW[512];
    for (int i = threadIdx.x; i < 512; i += blockDim.x) sW[i] = W[i];
    __syncthreads();
    int g = blockIdx.x * blockDim.x + threadIdx.x;
    if (g >= G) return;
    const float4* row = (const float4*)(g_c2 + (size_t)g * 256);
    float a0 = b[0], a1 = b[1];
#pragma unroll 8
    for (int i = 0; i < 64; i++) {
        float4 v = row[i];
        int o = i * 4;
        a0 += v.x * sW[2 * o + 0] + v.y * sW[2 * o + 2] + v.z * sW[2 * o + 4] + v.w * sW[2 * o + 6];
        a1 += v.x * sW[2 * o + 1] + v.y * sW[2 * o + 3] + v.z * sW[2 * o + 5] + v.w * sW[2 * o + 7];
    }
    out[g * 2 + 0] = a0;
    out[g * 2 + 1] = a1;
}

// ---------------- launch ----------------
extern "C" void kernel_launch(void* const* d_in, const int* in_sizes, int n_in,
                              void* d_out, int out_size) {
    const float* x_a = (const float*)d_in[0];
    const int* ei_a = (const int*)d_in[1];
    const int* batch_a = (const int*)d_in[2];
    const float* x_b = (const float*)d_in[3];
    const int* ei_b = (const int*)d_in[4];
    const int* batch_b = (const int*)d_in[5];
    const float* W1s = (const float*)d_in[6];
    const float* b1s = (const float*)d_in[7];
    const float* W2s = (const float*)d_in[8];
    const float* b2s = (const float*)d_in[9];
    const float* gammas = (const float*)d_in[10];
    const float* betas = (const float*)d_in[11];
    const float* fcxW = (const float*)d_in[12];
    const float* fcxb = (const float*)d_in[13];
    const float* fc1W = (const float*)d_in[14];
    const float* fc1b = (const float*)d_in[15];
    const float* fc2W = (const float*)d_in[16];
    const float* fc2b = (const float*)d_in[17];
    const float* outW = (const float*)d_in[18];
    const float* outb = (const float*)d_in[19];

    int N = in_sizes[0] / DIM;
    int E = in_sizes[1] / 2;
    int G = out_size / 2;
    int NN = 2 * N;
    float invN = 1.f / (float)N;
    int NPBh = (N + 127) / 128;

    float* sums_ptr;
    float* ha_ptr;
    float* c1_ptr;
    float* c2_ptr;
    float* partial_ptr;
    cudaGetSymbolAddress((void**)&sums_ptr, g_sums);
    cudaGetSymbolAddress((void**)&ha_ptr, g_ha);
    cudaGetSymbolAddress((void**)&c1_ptr, g_c1);
    cudaGetSymbolAddress((void**)&c2_ptr, g_c2);
    cudaGetSymbolAddress((void**)&partial_ptr, g_partial);

    k_zero<<<2048, 256>>>(x_a, x_b, N, G);
    k_count<<<2048, 256>>>(ei_a + E, ei_b + E, E, N);
    k_assign<<<(NN + 511) / 512, 512>>>(NN);
    k_fill<<<2048, 256>>>(ei_a, ei_a + E, ei_b, ei_b + E, E, N);

    for (int l = 0; l < 5; l++) {
        k_gather<<<(NN * 8 + 255) / 256, 256>>>(NN);
        const float* sA = (l == 0) ? nullptr : sums_ptr + (l - 1) * 128;
        const float* sB = (l == 0) ? nullptr : sums_ptr + (l - 1) * 128 + 64;
        const float* gP = (l == 0) ? nullptr : gammas + (l - 1) * DIM;
        const float* bP = (l == 0) ? nullptr : betas + (l - 1) * DIM;
        const int* pA = (l == 4) ? batch_a : nullptr;
        const int* pB = (l == 4) ? batch_b : nullptr;
        k_mlp<<<2 * NPBh, 128>>>(W1s + l * DIM * DIM, b1s + l * DIM,
                                 W2s + l * DIM * DIM, b2s + l * DIM,
                                 gP, bP, sA, sB, partial_ptr, pA, pB,
                                 N, G, NPBh, invN);
        k_reduce<<<128, 256>>>(sums_ptr + l * 128, NPBh);
    }

    k_fcbr<<<2 * G, 256>>>(fcxW, fcxb, gammas + 4 * DIM, betas + 4 * DIM,
                           ha_ptr, G, invN);

    dim3 g1(1024 / 64, G / 64);
    k_gemm<true, true><<<g1, 256>>>(ha_ptr, ha_ptr + (size_t)G * 256, fc1W, fc1b,
                                    c1_ptr, G, 1024, 256);
    dim3 g2(256 / 64, G / 64);
    k_gemm<false, true><<<g2, 256>>>(c1_ptr, nullptr, fc2W, fc2b, c2_ptr, G, 256, 1024);
    k_out<<<(G + 255) / 256, 256>>>(outW, outb, (float*)d_out, G);
}